// round 7
// baseline (speedup 1.0000x reference)
#include <cuda_runtime.h>
#include <cuda_fp16.h>

// ---------------------------------------------------------------------------
// HeteroRGCN layer, atomic-free CSR formulation:
//   mean_dst(W x_src + b) = W * mean_dst(x_src) + b   (b masked where deg==0)
// 7 launches:
//   1. prep: zero counters + convert features fp32 -> fp16
//   2. histogram dst degrees        3. scan phase 1
//   4. scan phase 2 (+cursor init)  5. reorder edges by dst
//   6. segment-mean of fp16 features (warp/node, 4 edge-groups, fp32 acc)
//   7. Linear on the means, bias masked by deg>0, -> d_out
// ---------------------------------------------------------------------------

#define MAXN 100000
#define MAXE 1000000
#define SCAN_B 256

// rel 1 (clicks): dst = items.   rel 2 (clicked_by): dst = users.
__device__ int    g_off1[MAXN + 1];
__device__ int    g_off2[MAXN + 1];
__device__ int    g_cur1[MAXN + 1];
__device__ int    g_cur2[MAXN + 1];
__device__ int    g_csr1[MAXE];
__device__ int    g_csr2[MAXE];
__device__ int    g_bsum1[512];
__device__ int    g_bsum2[512];
__device__ uint2  g_f16u[MAXN * 16];     // feat_user in fp16 (row = 16 uint2 = 128B)
__device__ uint2  g_f16i[MAXN * 16];     // feat_item in fp16
__device__ float  g_tmp_item[MAXN * 64]; // mean feat_user at item dsts
__device__ float  g_tmp_user[MAXN * 64]; // mean feat_item at user dsts

// ---------------------------------------------------------------------------
// prep: zero CSR counters AND convert both feature matrices to fp16.
// Thread i: converts float4 #i of each matrix (4 floats -> 8 bytes).
// ---------------------------------------------------------------------------
__global__ void prep_kernel(const float4* __restrict__ fu,
                            const float4* __restrict__ fi,
                            int n_user, int n_item) {
    int i = blockIdx.x * blockDim.x + threadIdx.x;
    if (i <= n_item) g_off1[i] = 0;
    if (i <= n_user) g_off2[i] = 0;

    if (i < n_user * 16) {
        float4 v = __ldg(fu + i);
        __half2 h0 = __float22half2_rn(make_float2(v.x, v.y));
        __half2 h1 = __float22half2_rn(make_float2(v.z, v.w));
        uint2 u;
        u.x = *reinterpret_cast<unsigned*>(&h0);
        u.y = *reinterpret_cast<unsigned*>(&h1);
        g_f16u[i] = u;
    }
    if (i < n_item * 16) {
        float4 v = __ldg(fi + i);
        __half2 h0 = __float22half2_rn(make_float2(v.x, v.y));
        __half2 h1 = __float22half2_rn(make_float2(v.z, v.w));
        uint2 u;
        u.x = *reinterpret_cast<unsigned*>(&h0);
        u.y = *reinterpret_cast<unsigned*>(&h1);
        g_f16i[i] = u;
    }
}

__global__ void hist_kernel(const int* __restrict__ dst1, int E1,
                            const int* __restrict__ dst2, int E2) {
    int i = blockIdx.x * blockDim.x + threadIdx.x;
    if (i < E1) atomicAdd(&g_off1[__ldg(dst1 + i) + 1], 1);
    if (i < E2) atomicAdd(&g_off2[__ldg(dst2 + i) + 1], 1);
}

// Scan phase 1: per-block inclusive scan + block sums. Both relations.
__global__ void scan_block(int nb1, int n1, int n2) {
    __shared__ int s[SCAN_B];
    int sel = (blockIdx.x >= nb1) ? 1 : 0;
    int blk = sel ? blockIdx.x - nb1 : blockIdx.x;
    int n   = sel ? n2 : n1;
    int* data = sel ? g_off2 : g_off1;
    int* bsum = sel ? g_bsum2 : g_bsum1;

    int t = threadIdx.x;
    int i = blk * SCAN_B + t;
    s[t] = (i < n) ? data[i] : 0;
    __syncthreads();
#pragma unroll
    for (int d = 1; d < SCAN_B; d <<= 1) {
        int x = (t >= d) ? s[t - d] : 0;
        __syncthreads();
        s[t] += x;
        __syncthreads();
    }
    if (i < n) data[i] = s[t];
    if (t == SCAN_B - 1) bsum[blk] = s[t];
}

// Scan phase 2: each block self-computes its prefix over the block sums,
// adds it, and initializes the reorder cursor.
__global__ void scan_add(int nb1, int n1, int n2) {
    __shared__ int sb[SCAN_B];
    int sel = (blockIdx.x >= nb1) ? 1 : 0;
    int blk = sel ? blockIdx.x - nb1 : blockIdx.x;
    int n   = sel ? n2 : n1;
    int* data = sel ? g_off2 : g_off1;
    int* cur  = sel ? g_cur2 : g_cur1;
    const int* bsum = sel ? g_bsum2 : g_bsum1;

    int t = threadIdx.x;
    int partial = 0;
    for (int j = t; j < blk; j += SCAN_B) partial += bsum[j];
    sb[t] = partial;
    __syncthreads();
#pragma unroll
    for (int d = SCAN_B / 2; d > 0; d >>= 1) {
        if (t < d) sb[t] += sb[t + d];
        __syncthreads();
    }
    int base = sb[0];

    int i = blk * SCAN_B + t;
    if (i < n) {
        int v = data[i] + base;
        data[i] = v;
        cur[i]  = v;
    }
}

__global__ void reorder_kernel(const int* __restrict__ s1, const int* __restrict__ d1, int E1,
                               const int* __restrict__ s2, const int* __restrict__ d2, int E2) {
    int i = blockIdx.x * blockDim.x + threadIdx.x;
    if (i < E1) {
        int p = atomicAdd(&g_cur1[__ldg(d1 + i)], 1);
        g_csr1[p] = __ldg(s1 + i);
    }
    if (i < E2) {
        int p = atomicAdd(&g_cur2[__ldg(d2 + i)], 1);
        g_csr2[p] = __ldg(s2 + i);
    }
}

// ---------------------------------------------------------------------------
// Segment-mean of fp16 features, fp32 accumulation. One warp per dst node.
// A fp16 row = 128B = 8 lanes x uint4(16B = 8 halves). The warp's 4 groups of
// 8 lanes each take a CONTIGUOUS quarter of the segment, unrolled x2 ->
// up to 8 feature loads in flight per warp. Cross-group shfl reduce.
// Grid: warps [0, n_item) -> rel1, [n_item, n_item+n_user) -> rel2.
// ---------------------------------------------------------------------------
__global__ __launch_bounds__(256) void segmean_kernel(int n_item, int n_user) {
    int gw = (blockIdx.x * blockDim.x + threadIdx.x) >> 5;
    int lane = threadIdx.x & 31;
    if (gw >= n_item + n_user) return;

    int sel = (gw >= n_item) ? 1 : 0;
    int w   = sel ? gw - n_item : gw;
    const int*   csr  = sel ? g_csr2 : g_csr1;
    const int*   off  = sel ? g_off2 : g_off1;
    const uint4* feat = sel ? (const uint4*)g_f16i : (const uint4*)g_f16u;
    float4*      tmp  = sel ? (float4*)g_tmp_user : (float4*)g_tmp_item;

    int beg = __ldg(off + w), end = __ldg(off + w + 1);
    int cnt = end - beg;
    int grp = lane >> 3;          // 0..3: edge group
    int q   = lane & 7;           // 16B chunk within the 128B row

    // contiguous quarter split
    int cq  = (cnt + 3) >> 2;
    int s0_ = grp * cq;
    int myb = beg + s0_;
    int myc = cnt - s0_;
    if (myc > cq) myc = cq;
    if (myc < 0)  myc = 0;

    float a[8], b[8];
#pragma unroll
    for (int k = 0; k < 8; k++) { a[k] = 0.f; b[k] = 0.f; }

    int i = 0;
    for (; i + 2 <= myc; i += 2) {
        int e0 = __ldg(csr + myb + i);
        int e1 = __ldg(csr + myb + i + 1);
        uint4 p0 = __ldg(feat + (long long)e0 * 8 + q);
        uint4 p1 = __ldg(feat + (long long)e1 * 8 + q);
        const __half2* h0 = reinterpret_cast<const __half2*>(&p0);
        const __half2* h1 = reinterpret_cast<const __half2*>(&p1);
#pragma unroll
        for (int k = 0; k < 4; k++) {
            float2 f0 = __half22float2(h0[k]);
            float2 f1 = __half22float2(h1[k]);
            a[2 * k + 0] += f0.x; a[2 * k + 1] += f0.y;
            b[2 * k + 0] += f1.x; b[2 * k + 1] += f1.y;
        }
    }
    if (i < myc) {
        int e0 = __ldg(csr + myb + i);
        uint4 p0 = __ldg(feat + (long long)e0 * 8 + q);
        const __half2* h0 = reinterpret_cast<const __half2*>(&p0);
#pragma unroll
        for (int k = 0; k < 4; k++) {
            float2 f0 = __half22float2(h0[k]);
            a[2 * k + 0] += f0.x; a[2 * k + 1] += f0.y;
        }
    }

#pragma unroll
    for (int k = 0; k < 8; k++) a[k] += b[k];
    // combine the 4 groups (lanes q, q+8, q+16, q+24 hold same columns)
#pragma unroll
    for (int k = 0; k < 8; k++) {
        a[k] += __shfl_xor_sync(0xffffffffu, a[k], 8);
        a[k] += __shfl_xor_sync(0xffffffffu, a[k], 16);
    }

    if (lane < 8) {
        float inv = (cnt > 0) ? 1.0f / (float)cnt : 0.0f;
#pragma unroll
        for (int k = 0; k < 8; k++) a[k] *= inv;
        float4 o0 = make_float4(a[0], a[1], a[2], a[3]);
        float4 o1 = make_float4(a[4], a[5], a[6], a[7]);
        tmp[(long long)w * 16 + 2 * q + 0] = o0;
        tmp[(long long)w * 16 + 2 * q + 1] = o1;
    }
}

// ---------------------------------------------------------------------------
// out = X @ W^T + (deg>0 ? b : 0), both relations via blockIdx.y.
// Block: 256 threads -> 16 rows x 64 cols, W + X tile in smem.
// ---------------------------------------------------------------------------
__global__ void linear_kernel(const float4* __restrict__ W1, const float* __restrict__ b1,
                              const float4* __restrict__ W2, const float* __restrict__ b2,
                              float* __restrict__ out_item, float* __restrict__ out_user,
                              int n_item, int n_user) {
    __shared__ float4 Ws[64][17];
    __shared__ float4 Xs[16][17];
    __shared__ float  bs[64];
    __shared__ int    mk[16];

    int sel = blockIdx.y;
    const float4* W   = sel ? W2 : W1;
    const float*  b   = sel ? b2 : b1;
    const float4* X   = sel ? (const float4*)g_tmp_user : (const float4*)g_tmp_item;
    const int*    off = sel ? g_off2 : g_off1;
    float*        out = sel ? out_user : out_item;
    int           N   = sel ? n_user : n_item;

    int row0 = blockIdx.x * 16;
    if (row0 >= N) return;

    int tid = threadIdx.x;
    for (int i = tid; i < 64 * 16; i += 256) Ws[i >> 4][i & 15] = W[i];
    if (tid < 64) bs[tid] = b[tid];
    if (tid < 16) {
        int r = row0 + tid;
        mk[tid] = (r < N && off[r + 1] > off[r]) ? 1 : 0;
    }
    {
        int r = tid >> 4, kk = tid & 15;
        int grow = row0 + r;
        Xs[r][kk] = (grow < N) ? X[(long long)grow * 16 + kk]
                               : make_float4(0.f, 0.f, 0.f, 0.f);
    }
    __syncthreads();

    int c = tid & 63;
    int rsub = tid >> 6;

    float acc0 = mk[4 * rsub + 0] ? bs[c] : 0.f;
    float acc1 = mk[4 * rsub + 1] ? bs[c] : 0.f;
    float acc2 = mk[4 * rsub + 2] ? bs[c] : 0.f;
    float acc3 = mk[4 * rsub + 3] ? bs[c] : 0.f;

#pragma unroll
    for (int k = 0; k < 16; k++) {
        float4 w  = Ws[c][k];
        float4 x0 = Xs[4 * rsub + 0][k];
        float4 x1 = Xs[4 * rsub + 1][k];
        float4 x2 = Xs[4 * rsub + 2][k];
        float4 x3 = Xs[4 * rsub + 3][k];
        acc0 += x0.x * w.x + x0.y * w.y + x0.z * w.z + x0.w * w.w;
        acc1 += x1.x * w.x + x1.y * w.y + x1.z * w.z + x1.w * w.w;
        acc2 += x2.x * w.x + x2.y * w.y + x2.z * w.z + x2.w * w.w;
        acc3 += x3.x * w.x + x3.y * w.y + x3.z * w.z + x3.w * w.w;
    }

    int rr = row0 + 4 * rsub;
    if (rr + 0 < N) out[(long long)(rr + 0) * 64 + c] = acc0;
    if (rr + 1 < N) out[(long long)(rr + 1) * 64 + c] = acc1;
    if (rr + 2 < N) out[(long long)(rr + 2) * 64 + c] = acc2;
    if (rr + 3 < N) out[(long long)(rr + 3) * 64 + c] = acc3;
}

// ---------------------------------------------------------------------------
extern "C" void kernel_launch(void* const* d_in, const int* in_sizes, int n_in,
                              void* d_out, int out_size) {
    const float* feat_user  = (const float*)d_in[0];
    const float* feat_item  = (const float*)d_in[1];
    const int*   src_clicks = (const int*)d_in[2];
    const int*   dst_clicks = (const int*)d_in[3];
    const int*   src_cb     = (const int*)d_in[4];
    const int*   dst_cb     = (const int*)d_in[5];
    const float* W_clicks   = (const float*)d_in[6];
    const float* b_clicks   = (const float*)d_in[7];
    const float* W_cb       = (const float*)d_in[8];
    const float* b_cb       = (const float*)d_in[9];

    int n_user = in_sizes[0] / 64;
    int n_item = in_sizes[1] / 64;
    int E1 = in_sizes[2];   // clicks edges      (user -> item)
    int E2 = in_sizes[4];   // clicked_by edges  (item -> user)
    int Emax = E1 > E2 ? E1 : E2;

    float* out_user = (float*)d_out;                         // [n_user, 64]
    float* out_item = out_user + (long long)n_user * 64;     // [n_item, 64]

    int n1 = n_item + 1, n2 = n_user + 1;
    int nb1 = (n1 + SCAN_B - 1) / SCAN_B;
    int nb2 = (n2 + SCAN_B - 1) / SCAN_B;
    int nmax = n_item > n_user ? n_item : n_user;

    // 1. prep: zero counters + fp16 conversion of both feature matrices
    {
        int threads = nmax * 16;           // covers counters (nmax+1) too
        prep_kernel<<<(threads + 255) / 256, 256>>>(
            (const float4*)feat_user, (const float4*)feat_item, n_user, n_item);
    }
    // 2. histogram
    hist_kernel<<<(Emax + 255) / 256, 256>>>(dst_clicks, E1, dst_cb, E2);
    // 3-4. scan
    scan_block<<<nb1 + nb2, SCAN_B>>>(nb1, n1, n2);
    scan_add<<<nb1 + nb2, SCAN_B>>>(nb1, n1, n2);
    // 5. reorder
    reorder_kernel<<<(Emax + 255) / 256, 256>>>(src_clicks, dst_clicks, E1,
                                                src_cb, dst_cb, E2);
    // 6. segment-mean (fp16 gather, fp32 accumulate; one warp per dst)
    {
        long long threads = (long long)(n_item + n_user) * 32;
        segmean_kernel<<<(int)((threads + 255) / 256), 256>>>(n_item, n_user);
    }
    // 7. Linear -> d_out
    {
        dim3 grid((nmax + 15) / 16, 2);
        linear_kernel<<<grid, 256>>>((const float4*)W_clicks, b_clicks,
                                     (const float4*)W_cb, b_cb,
                                     out_item, out_user, n_item, n_user);
    }
}